// round 15
// baseline (speedup 1.0000x reference)
#include <cuda_runtime.h>
#include <cuda_bf16.h>
#include <cstdint>
#include <math.h>

#define DD 1024
#define SS 2048
#define BB 8
#define BSROWS (BB * SS)   // 16384
typedef long long ll;

// ======================= device scratch (no allocations) ====================
__device__ __align__(16) float g_A[(ll)BB * SS * SS];                       // scores fp32 (128MB)
__device__ __align__(16) __nv_bfloat16 g_x2h[(ll)BSROWS * DD], g_x2l[(ll)BSROWS * DD];
__device__ __align__(16) __nv_bfloat16 g_q2h[DD * DD], g_q2l[DD * DD];
__device__ __align__(16) __nv_bfloat16 g_k2h[DD * DD], g_k2l[DD * DD];
__device__ __align__(16) __nv_bfloat16 g_mth[DD * DD], g_mtl[DD * DD];      // (Wk2 Wq2^T) hi/lo
__device__ __align__(16) __nv_bfloat16 g_wth[DD * DD], g_wtl[DD * DD];      // Wv2^T hi/lo
__device__ __align__(16) __nv_bfloat16 g_gh[(ll)BSROWS * DD], g_gl[(ll)BSROWS * DD];
__device__ __align__(16) __nv_bfloat16 g_vth[(ll)BB * DD * SS], g_vtl[(ll)BB * DD * SS]; // V^T
__device__ __align__(16) __nv_bfloat16 g_ph[(ll)BB * SS * SS], g_pl[(ll)BB * SS * SS];   // softmax hi/lo
__device__ __align__(16) float g_tvec[DD];
__device__ __align__(16) float g_vb1[BB * DD];
__device__ __align__(16) float g_sw[BB * SS];
__device__ __align__(16) float g_negV[BB * DD];

// ======================= base-ISA tensor-core helpers =======================
__device__ __forceinline__ uint32_t smem_u32(const void* p) {
    uint32_t a;
    asm("{ .reg .u64 t; cvta.to.shared.u64 t, %1; cvt.u32.u64 %0, t; }" : "=r"(a) : "l"(p));
    return a;
}

__device__ __forceinline__ void cpa16(uint32_t s, const void* g) {
    asm volatile("cp.async.cg.shared.global [%0], [%1], 16;" :: "r"(s), "l"(g));
}

#define LDSM_X4(r, addr) \
    asm volatile("ldmatrix.sync.aligned.m8n8.x4.shared.b16 {%0,%1,%2,%3}, [%4];" \
        : "=r"((r)[0]), "=r"((r)[1]), "=r"((r)[2]), "=r"((r)[3]) : "r"(addr))

#define MMA_BF16(d, a, b0, b1) \
    asm volatile("mma.sync.aligned.m16n8k16.row.col.f32.bf16.bf16.f32 " \
        "{%0,%1,%2,%3}, {%4,%5,%6,%7}, {%8,%9}, {%0,%1,%2,%3};" \
        : "+f"((d)[0]), "+f"((d)[1]), "+f"((d)[2]), "+f"((d)[3]) \
        : "r"((a)[0]), "r"((a)[1]), "r"((a)[2]), "r"((a)[3]), "r"(b0), "r"(b1))

__device__ __forceinline__ void split2(float v, __nv_bfloat16& h, __nv_bfloat16& l) {
    h = __float2bfloat16(v);
    l = __float2bfloat16(v - __bfloat162float(h));
}

// ======================= mma.sync split-bf16 GEMM ===========================
// D[m,n] = sum_k (Ah+Al)[m,k]*(Bh+Bl)[n,k]  (drops lo*lo term)
// MODE 0: fp32 out, C = acc*scale + bias[n]
// MODE 1: bf16 hi/lo out at [m*ldc + n]
// MODE 2: bf16 hi/lo out TRANSPOSED at [n*ldc + m], acc += bias[n] first
#define KT 64
#define NTHREADS 256
#define STAGE_B 65536     // 4 tiles x 16KB
#define NSTAGES 3
#define SMEM_SZ (NSTAGES * STAGE_B)   // 192KB

__device__ __forceinline__ void stage_load(uint32_t sb, int stage,
    const __nv_bfloat16* __restrict__ pAh, const __nv_bfloat16* __restrict__ pAl,
    const __nv_bfloat16* __restrict__ pBh, const __nv_bfloat16* __restrict__ pBl,
    int k0, int K, int tid)
{
    const uint32_t base = sb + stage * STAGE_B;
#pragma unroll
    for (int it = 0; it < 4; it++) {
        const int id = tid + it * NTHREADS;     // 0..1023
        const int row = id >> 3, c = id & 7;
        const uint32_t so = (uint32_t)(row * 128) + (((uint32_t)c << 4) ^ (((uint32_t)(row & 7)) << 4));
        const ll go = (ll)row * K + k0 + c * 8;
        cpa16(base +         so, pAh + go);
        cpa16(base + 16384 + so, pAl + go);
        cpa16(base + 32768 + so, pBh + go);
        cpa16(base + 49152 + so, pBl + go);
    }
    asm volatile("cp.async.commit_group;" ::: "memory");
}

template <int MODE>
__global__ void __launch_bounds__(NTHREADS)
mma_gemm(const __nv_bfloat16* __restrict__ Ah, const __nv_bfloat16* __restrict__ Al,
         const __nv_bfloat16* __restrict__ Bh, const __nv_bfloat16* __restrict__ Bl,
         int K, ll sA, ll sB,
         float* __restrict__ C0, __nv_bfloat16* __restrict__ Ch, __nv_bfloat16* __restrict__ Cl,
         ll sC, int ldc, float scale, const float* __restrict__ bias, ll sBias)
{
    extern __shared__ char smem[];
    const uint32_t sb = smem_u32(smem);
    const int tid = threadIdx.x, wid = tid >> 5, lane = tid & 31;
    const int m0 = blockIdx.y * 128, n0 = blockIdx.x * 128, bz = blockIdx.z;

    const __nv_bfloat16* pAh = Ah + (ll)bz * sA + (ll)m0 * K;
    const __nv_bfloat16* pAl = Al + (ll)bz * sA + (ll)m0 * K;
    const __nv_bfloat16* pBh = Bh + (ll)bz * sB + (ll)n0 * K;
    const __nv_bfloat16* pBl = Bl + (ll)bz * sB + (ll)n0 * K;

    const int wm = (wid >> 2) * 64;     // warp m offset (2 groups of 64)
    const int wn = (wid & 3) * 32;      // warp n offset (4 groups of 32)

    // ldmatrix lane addressing (swizzle xor depends only on row&7)
    const int a_row = lane & 15;
    const uint32_t a_cb = ((uint32_t)(lane >> 4)) << 4;
    const uint32_t swzA = ((uint32_t)(a_row & 7)) << 4;
    const int b_row = ((lane >> 4) << 3) + (lane & 7);
    const uint32_t b_cb = ((uint32_t)((lane >> 3) & 1)) << 4;
    const uint32_t swzB = ((uint32_t)(b_row & 7)) << 4;

    float acc[4][4][4];
#pragma unroll
    for (int i = 0; i < 4; i++)
#pragma unroll
        for (int j = 0; j < 4; j++)
#pragma unroll
            for (int e = 0; e < 4; e++) acc[i][j][e] = 0.f;

    const int nk = K / KT;
    stage_load(sb, 0, pAh, pAl, pBh, pBl, 0, K, tid);
    if (nk > 1) stage_load(sb, 1, pAh, pAl, pBh, pBl, KT, K, tid);

    int buf = 0;
    for (int kt = 0; kt < nk; kt++) {
        if (kt + 2 < nk) {
            int st = kt + 2;
            stage_load(sb, st - (st / NSTAGES) * NSTAGES, pAh, pAl, pBh, pBl, st * KT, K, tid);
            asm volatile("cp.async.wait_group 2;" ::: "memory");
        } else if (kt + 1 < nk) {
            asm volatile("cp.async.wait_group 1;" ::: "memory");
        } else {
            asm volatile("cp.async.wait_group 0;" ::: "memory");
        }
        __syncthreads();

        const uint32_t sbase = sb + buf * STAGE_B;
#pragma unroll
        for (int ks = 0; ks < 4; ks++) {
            const uint32_t kb = (uint32_t)(ks * 32);
            uint32_t ahf[4][4], alf[4][4], bhf[2][4], blf[2][4];
#pragma unroll
            for (int mt = 0; mt < 4; mt++) {
                const uint32_t ra = sbase + (uint32_t)((wm + mt * 16 + a_row) * 128)
                                  + ((kb + a_cb) ^ swzA);
                LDSM_X4(ahf[mt], ra);
                LDSM_X4(alf[mt], ra + 16384);
            }
#pragma unroll
            for (int g = 0; g < 2; g++) {
                const uint32_t rb = sbase + 32768 + (uint32_t)((wn + g * 16 + b_row) * 128)
                                  + ((kb + b_cb) ^ swzB);
                LDSM_X4(bhf[g], rb);
                LDSM_X4(blf[g], rb + 16384);
            }
            // term-major issue: 16 independent MMAs per term sweep (no acc RAW
            // between consecutive instructions -> HMMA latency fully hidden)
#pragma unroll
            for (int mt = 0; mt < 4; mt++)
#pragma unroll
                for (int nt = 0; nt < 4; nt++) {
                    const uint32_t* bh2 = &bhf[nt >> 1][(nt & 1) * 2];
                    MMA_BF16(acc[mt][nt], ahf[mt], bh2[0], bh2[1]);
                }
#pragma unroll
            for (int mt = 0; mt < 4; mt++)
#pragma unroll
                for (int nt = 0; nt < 4; nt++) {
                    const uint32_t* bl2 = &blf[nt >> 1][(nt & 1) * 2];
                    MMA_BF16(acc[mt][nt], ahf[mt], bl2[0], bl2[1]);
                }
#pragma unroll
            for (int mt = 0; mt < 4; mt++)
#pragma unroll
                for (int nt = 0; nt < 4; nt++) {
                    const uint32_t* bh2 = &bhf[nt >> 1][(nt & 1) * 2];
                    MMA_BF16(acc[mt][nt], alf[mt], bh2[0], bh2[1]);
                }
        }
        __syncthreads();
        buf++;
        if (buf == NSTAGES) buf = 0;
    }

    // ---------------- epilogue (accumulators in registers) ----------------
    const int er = lane >> 2;          // 0..7
    const int ec = (lane & 3) * 2;     // 0,2,4,6
#pragma unroll
    for (int mt = 0; mt < 4; mt++) {
#pragma unroll
        for (int nt = 0; nt < 4; nt++) {
            const float* a4 = acc[mt][nt];
            const int mA = m0 + wm + mt * 16 + er;
            const int nA = n0 + wn + nt * 8 + ec;
            if (MODE == 0) {
                const float2 bb = *reinterpret_cast<const float2*>(bias + (ll)bz * sBias + nA);
                float2 v0, v1;
                v0.x = a4[0] * scale + bb.x;
                v0.y = a4[1] * scale + bb.y;
                v1.x = a4[2] * scale + bb.x;
                v1.y = a4[3] * scale + bb.y;
                *reinterpret_cast<float2*>(C0 + (ll)bz * sC + (ll)mA * ldc + nA) = v0;
                *reinterpret_cast<float2*>(C0 + (ll)bz * sC + (ll)(mA + 8) * ldc + nA) = v1;
            } else if (MODE == 1) {
                __nv_bfloat16 h0, l0, h1, l1;
                split2(a4[0], h0, l0);
                split2(a4[1], h1, l1);
                __nv_bfloat162 hv, lv;
                hv.x = h0; hv.y = h1; lv.x = l0; lv.y = l1;
                const ll c0 = (ll)bz * sC + (ll)mA * ldc + nA;
                *reinterpret_cast<__nv_bfloat162*>(Ch + c0) = hv;
                *reinterpret_cast<__nv_bfloat162*>(Cl + c0) = lv;
                split2(a4[2], h0, l0);
                split2(a4[3], h1, l1);
                hv.x = h0; hv.y = h1; lv.x = l0; lv.y = l1;
                const ll c1 = (ll)bz * sC + (ll)(mA + 8) * ldc + nA;
                *reinterpret_cast<__nv_bfloat162*>(Ch + c1) = hv;
                *reinterpret_cast<__nv_bfloat162*>(Cl + c1) = lv;
            } else {
                const float b0 = bias[(ll)bz * sBias + nA];
                const float b1 = bias[(ll)bz * sBias + nA + 1];
                __nv_bfloat16 h, l;
                const ll base = (ll)bz * sC;
                split2(a4[0] + b0, h, l);
                Ch[base + (ll)nA * ldc + mA] = h;       Cl[base + (ll)nA * ldc + mA] = l;
                split2(a4[1] + b1, h, l);
                Ch[base + (ll)(nA + 1) * ldc + mA] = h; Cl[base + (ll)(nA + 1) * ldc + mA] = l;
                split2(a4[2] + b0, h, l);
                Ch[base + (ll)nA * ldc + mA + 8] = h;       Cl[base + (ll)nA * ldc + mA + 8] = l;
                split2(a4[3] + b1, h, l);
                Ch[base + (ll)(nA + 1) * ldc + mA + 8] = h; Cl[base + (ll)(nA + 1) * ldc + mA + 8] = l;
            }
        }
    }
}

// ======================= small helper kernels ===============================
__global__ void split_kernel(const float* __restrict__ src, __nv_bfloat16* __restrict__ hi,
                             __nv_bfloat16* __restrict__ lo, ll n4)
{
    ll i = (ll)blockIdx.x * blockDim.x + threadIdx.x;
    const ll stride = (ll)gridDim.x * blockDim.x;
    for (; i < n4; i += stride) {
        float4 v = reinterpret_cast<const float4*>(src)[i];
        __nv_bfloat16 h0, h1, h2, h3, l0, l1, l2, l3;
        split2(v.x, h0, l0); split2(v.y, h1, l1);
        split2(v.z, h2, l2); split2(v.w, h3, l3);
        __nv_bfloat162 a, b, c, d;
        a.x = h0; a.y = h1; b.x = h2; b.y = h3;
        c.x = l0; c.y = l1; d.x = l2; d.y = l3;
        reinterpret_cast<__nv_bfloat162*>(hi)[i * 2 + 0] = a;
        reinterpret_cast<__nv_bfloat162*>(hi)[i * 2 + 1] = b;
        reinterpret_cast<__nv_bfloat162*>(lo)[i * 2 + 0] = c;
        reinterpret_cast<__nv_bfloat162*>(lo)[i * 2 + 1] = d;
    }
}

// Wt[n,e] = Wv[D+e, n]  (transpose + split)
__global__ void tsplit_wv(const float* __restrict__ Wv, __nv_bfloat16* __restrict__ Wth,
                          __nv_bfloat16* __restrict__ Wtl)
{
    __shared__ float t[32][33];
    const int tx = threadIdx.x, ty = threadIdx.y;
    const int bx = blockIdx.x, by = blockIdx.y;
    const int x = bx * 32 + tx;
#pragma unroll
    for (int j = 0; j < 4; j++) {
        const int y = by * 32 + ty + j * 8;
        t[ty + j * 8][tx] = Wv[(ll)(DD + y) * DD + x];
    }
    __syncthreads();
#pragma unroll
    for (int j = 0; j < 4; j++) {
        const int n = bx * 32 + ty + j * 8;
        const int d = by * 32 + tx;
        __nv_bfloat16 h, l;
        split2(t[tx][ty + j * 8], h, l);
        Wth[(ll)n * DD + d] = h;
        Wtl[(ll)n * DD + d] = l;
    }
}

__global__ void rowdot_kernel(const float* __restrict__ X, const float* __restrict__ vec,
                              float* __restrict__ out, int nrows, float scale)
{
    const int warp = (blockIdx.x * blockDim.x + threadIdx.x) >> 5;
    const int lane = threadIdx.x & 31;
    if (warp >= nrows) return;
    const float4* r = reinterpret_cast<const float4*>(X + (ll)warp * DD);
    const float4* v = reinterpret_cast<const float4*>(vec);
    float acc = 0.f;
#pragma unroll
    for (int i = 0; i < 8; i++) {
        float4 a = r[lane + 32 * i];
        float4 b = v[lane + 32 * i];
        acc += a.x * b.x + a.y * b.y + a.z * b.z + a.w * b.w;
    }
#pragma unroll
    for (int off = 16; off; off >>= 1)
        acc += __shfl_xor_sync(0xffffffffu, acc, off);
    if (lane == 0) out[warp] = scale * acc;
}

__global__ void vb1_kernel(const float* __restrict__ X1, const float* __restrict__ Wv,
                           const float* __restrict__ bv, float* __restrict__ vb1)
{
    __shared__ float x1s[BB * DD];
    const int tid = threadIdx.x;  // 128
    for (int i = tid; i < BB * DD; i += 128) x1s[i] = X1[i];
    __syncthreads();
    const int o = blockIdx.x * 128 + tid;
    float acc[BB];
#pragma unroll
    for (int b = 0; b < BB; b++) acc[b] = 0.f;
    for (int i = 0; i < DD; i++) {
        const float wv = Wv[(ll)i * DD + o];
#pragma unroll
        for (int b = 0; b < BB; b++) acc[b] = fmaf(x1s[b * DD + i], wv, acc[b]);
    }
    const float bvo = bv[o];
#pragma unroll
    for (int b = 0; b < BB; b++) vb1[b * DD + o] = acc[b] + bvo;
}

// row softmax over 2048 fp32 scores -> bf16 hi/lo probs
__global__ void __launch_bounds__(256) softmax_rows(const float* __restrict__ A,
                                                    __nv_bfloat16* __restrict__ Ph,
                                                    __nv_bfloat16* __restrict__ Pl)
{
    const float* p = A + (ll)blockIdx.x * SS;
    const int tid = threadIdx.x;
    const int lane = tid & 31, wid = tid >> 5;
    const float4* pv = reinterpret_cast<const float4*>(p);
    float4 v0 = pv[tid];
    float4 v1 = pv[tid + 256];

    float m = fmaxf(fmaxf(fmaxf(v0.x, v0.y), fmaxf(v0.z, v0.w)),
                    fmaxf(fmaxf(v1.x, v1.y), fmaxf(v1.z, v1.w)));
#pragma unroll
    for (int off = 16; off; off >>= 1) m = fmaxf(m, __shfl_xor_sync(0xffffffffu, m, off));
    __shared__ float smax[8], ssum[8];
    if (lane == 0) smax[wid] = m;
    __syncthreads();
    float mall = smax[0];
#pragma unroll
    for (int i = 1; i < 8; i++) mall = fmaxf(mall, smax[i]);

    v0.x = __expf(v0.x - mall); v0.y = __expf(v0.y - mall);
    v0.z = __expf(v0.z - mall); v0.w = __expf(v0.w - mall);
    v1.x = __expf(v1.x - mall); v1.y = __expf(v1.y - mall);
    v1.z = __expf(v1.z - mall); v1.w = __expf(v1.w - mall);

    float s = v0.x + v0.y + v0.z + v0.w + v1.x + v1.y + v1.z + v1.w;
#pragma unroll
    for (int off = 16; off; off >>= 1) s += __shfl_xor_sync(0xffffffffu, s, off);
    if (lane == 0) ssum[wid] = s;
    __syncthreads();
    float tot = 0.f;
#pragma unroll
    for (int i = 0; i < 8; i++) tot += ssum[i];
    const float inv = 1.f / tot;

    __nv_bfloat162* ph = reinterpret_cast<__nv_bfloat162*>(Ph + (ll)blockIdx.x * SS);
    __nv_bfloat162* pl = reinterpret_cast<__nv_bfloat162*>(Pl + (ll)blockIdx.x * SS);

    auto emit = [&](float a, float b, int idx) {
        __nv_bfloat16 ah, al, bh, bl;
        split2(a * inv, ah, al);
        split2(b * inv, bh, bl);
        __nv_bfloat162 hv; hv.x = ah; hv.y = bh;
        __nv_bfloat162 lv; lv.x = al; lv.y = bl;
        ph[idx] = hv;
        pl[idx] = lv;
    };
    emit(v0.x, v0.y, tid * 2 + 0);
    emit(v0.z, v0.w, tid * 2 + 1);
    emit(v1.x, v1.y, 512 + tid * 2 + 0);
    emit(v1.z, v1.w, 512 + tid * 2 + 1);
}

// negV[b,n] = -(alpha/S) * sum_k Vt[b,n,k]
__global__ void vtsum_kernel(const __nv_bfloat16* __restrict__ Vth,
                             const __nv_bfloat16* __restrict__ Vtl,
                             const float* __restrict__ alpha, float* __restrict__ negV)
{
    const int row = blockIdx.x * 8 + (threadIdx.x >> 5);
    const int lane = threadIdx.x & 31;
    const __nv_bfloat162* ph = reinterpret_cast<const __nv_bfloat162*>(Vth + (ll)row * SS);
    const __nv_bfloat162* pl = reinterpret_cast<const __nv_bfloat162*>(Vtl + (ll)row * SS);
    float acc = 0.f;
#pragma unroll
    for (int i = 0; i < 32; i++) {
        __nv_bfloat162 a = ph[lane + 32 * i];
        __nv_bfloat162 b = pl[lane + 32 * i];
        acc += __bfloat162float(a.x) + __bfloat162float(a.y)
             + __bfloat162float(b.x) + __bfloat162float(b.y);
    }
#pragma unroll
    for (int off = 16; off; off >>= 1)
        acc += __shfl_xor_sync(0xffffffffu, acc, off);
    if (lane == 0) negV[row] = -(alpha[0] / (float)SS) * acc;
}

// ======================= launch =============================================
extern "C" void kernel_launch(void* const* d_in, const int* in_sizes, int n_in,
                              void* d_out, int out_size)
{
    (void)in_sizes; (void)n_in; (void)out_size;
    const float* X1   = (const float*)d_in[0];
    const float* X2   = (const float*)d_in[1];
    const float* Wq2  = (const float*)d_in[4];
    const float* bq2  = (const float*)d_in[5];
    const float* Wk2  = (const float*)d_in[8];
    const float* Wv   = (const float*)d_in[10];
    const float* bv   = (const float*)d_in[11];
    const float* alph = (const float*)d_in[12];
    float* out = (float*)d_out;
    const float s = 0.03125f;  // 1/sqrt(1024)

    cudaFuncSetAttribute(mma_gemm<0>, cudaFuncAttributeMaxDynamicSharedMemorySize, SMEM_SZ);
    cudaFuncSetAttribute(mma_gemm<1>, cudaFuncAttributeMaxDynamicSharedMemorySize, SMEM_SZ);
    cudaFuncSetAttribute(mma_gemm<2>, cudaFuncAttributeMaxDynamicSharedMemorySize, SMEM_SZ);

    void* p;
    cudaGetSymbolAddress(&p, g_A);    float* pA   = (float*)p;
    cudaGetSymbolAddress(&p, g_x2h);  __nv_bfloat16* x2h = (__nv_bfloat16*)p;
    cudaGetSymbolAddress(&p, g_x2l);  __nv_bfloat16* x2l = (__nv_bfloat16*)p;
    cudaGetSymbolAddress(&p, g_q2h);  __nv_bfloat16* q2h = (__nv_bfloat16*)p;
    cudaGetSymbolAddress(&p, g_q2l);  __nv_bfloat16* q2l = (__nv_bfloat16*)p;
    cudaGetSymbolAddress(&p, g_k2h);  __nv_bfloat16* k2h = (__nv_bfloat16*)p;
    cudaGetSymbolAddress(&p, g_k2l);  __nv_bfloat16* k2l = (__nv_bfloat16*)p;
    cudaGetSymbolAddress(&p, g_mth);  __nv_bfloat16* mth = (__nv_bfloat16*)p;
    cudaGetSymbolAddress(&p, g_mtl);  __nv_bfloat16* mtl = (__nv_bfloat16*)p;
    cudaGetSymbolAddress(&p, g_wth);  __nv_bfloat16* wth = (__nv_bfloat16*)p;
    cudaGetSymbolAddress(&p, g_wtl);  __nv_bfloat16* wtl = (__nv_bfloat16*)p;
    cudaGetSymbolAddress(&p, g_gh);   __nv_bfloat16* gh  = (__nv_bfloat16*)p;
    cudaGetSymbolAddress(&p, g_gl);   __nv_bfloat16* gl  = (__nv_bfloat16*)p;
    cudaGetSymbolAddress(&p, g_vth);  __nv_bfloat16* vth = (__nv_bfloat16*)p;
    cudaGetSymbolAddress(&p, g_vtl);  __nv_bfloat16* vtl = (__nv_bfloat16*)p;
    cudaGetSymbolAddress(&p, g_ph);   __nv_bfloat16* ph  = (__nv_bfloat16*)p;
    cudaGetSymbolAddress(&p, g_pl);   __nv_bfloat16* pl  = (__nv_bfloat16*)p;
    cudaGetSymbolAddress(&p, g_tvec); float* ptvec = (float*)p;
    cudaGetSymbolAddress(&p, g_vb1);  float* pvb1  = (float*)p;
    cudaGetSymbolAddress(&p, g_sw);   float* psw   = (float*)p;
    cudaGetSymbolAddress(&p, g_negV); float* pnegV = (float*)p;

    // --- input conversions / small precomputes ---
    split_kernel<<<64, 256>>>(Wq2, q2h, q2l, (ll)DD * DD / 4);
    split_kernel<<<64, 256>>>(Wk2, k2h, k2l, (ll)DD * DD / 4);
    split_kernel<<<2048, 256>>>(X2, x2h, x2l, (ll)BSROWS * DD / 4);
    tsplit_wv<<<dim3(32, 32), dim3(32, 8)>>>(Wv, wth, wtl);
    rowdot_kernel<<<DD / 8, 256>>>(Wk2, bq2, ptvec, DD, 1.f);
    vb1_kernel<<<DD / 128, 128>>>(X1, Wv, bv, pvb1);
    rowdot_kernel<<<BSROWS / 8, 256>>>(X2, ptvec, psw, BSROWS, s);

    // --- Mt = Wk2 @ Wq2^T  -> hi/lo ---
    mma_gemm<1><<<dim3(8, 8, 1), NTHREADS, SMEM_SZ>>>(
        k2h, k2l, q2h, q2l, DD, 0, 0,
        nullptr, mth, mtl, 0, DD, 1.f, nullptr, 0);

    // --- G = X2 @ M (B = Mt rows, K-major) -> hi/lo ---
    mma_gemm<1><<<dim3(8, 16, 8), NTHREADS, SMEM_SZ>>>(
        x2h, x2l, mth, mtl, DD, (ll)SS * DD, 0,
        nullptr, gh, gl, (ll)SS * DD, DD, 1.f, nullptr, 0);

    // --- V = X2 @ Wv2 + vb1  -> transposed hi/lo [b][d][s] ---
    mma_gemm<2><<<dim3(8, 16, 8), NTHREADS, SMEM_SZ>>>(
        x2h, x2l, wth, wtl, DD, (ll)SS * DD, 0,
        nullptr, vth, vtl, (ll)DD * SS, SS, 1.f, pvb1, DD);

    // --- negV from Vt row sums ---
    vtsum_kernel<<<1024, 256>>>(vth, vtl, alph, pnegV);

    // --- scores = s*(G @ X2^T) + sw[k]  (fp32) ---
    mma_gemm<0><<<dim3(16, 16, 8), NTHREADS, SMEM_SZ>>>(
        gh, gl, x2h, x2l, DD, (ll)SS * DD, (ll)SS * DD,
        pA, nullptr, nullptr, (ll)SS * SS, SS, s, psw, SS);

    // --- softmax -> P hi/lo ---
    softmax_rows<<<BSROWS, 256>>>(pA, ph, pl);

    // --- out = P @ V + negV ---
    mma_gemm<0><<<dim3(8, 16, 8), NTHREADS, SMEM_SZ>>>(
        ph, pl, vth, vtl, SS, (ll)SS * SS, (ll)DD * SS,
        out, nullptr, nullptr, (ll)SS * DD, DD, 1.f, pnegV, DD);
}

// round 16
// speedup vs baseline: 1.1095x; 1.1095x over previous
#include <cuda_runtime.h>
#include <cuda_bf16.h>
#include <cstdint>
#include <math.h>

#define DD 1024
#define SS 2048
#define BB 8
#define BSROWS (BB * SS)   // 16384
typedef long long ll;

// ======================= device scratch (no allocations) ====================
__device__ __align__(16) float g_A[(ll)BB * SS * SS];                       // scores fp32 (128MB)
__device__ __align__(16) __nv_bfloat16 g_x2h[(ll)BSROWS * DD], g_x2l[(ll)BSROWS * DD];
__device__ __align__(16) __nv_bfloat16 g_q2h[DD * DD], g_q2l[DD * DD];
__device__ __align__(16) __nv_bfloat16 g_k2h[DD * DD], g_k2l[DD * DD];
__device__ __align__(16) __nv_bfloat16 g_mth[DD * DD], g_mtl[DD * DD];      // (Wk2 Wq2^T) hi/lo
__device__ __align__(16) __nv_bfloat16 g_wth[DD * DD], g_wtl[DD * DD];      // Wv2^T hi/lo
__device__ __align__(16) __nv_bfloat16 g_gh[(ll)BSROWS * DD], g_gl[(ll)BSROWS * DD];
__device__ __align__(16) __nv_bfloat16 g_vth[(ll)BB * DD * SS], g_vtl[(ll)BB * DD * SS]; // V^T
__device__ __align__(16) __nv_bfloat16 g_ph[(ll)BB * SS * SS], g_pl[(ll)BB * SS * SS];   // softmax hi/lo
__device__ __align__(16) float g_tvec[DD];
__device__ __align__(16) float g_vb1[BB * DD];
__device__ __align__(16) float g_sw[BB * SS];
__device__ __align__(16) float g_negV[BB * DD];

// ======================= base-ISA tensor-core helpers =======================
__device__ __forceinline__ uint32_t smem_u32(const void* p) {
    uint32_t a;
    asm("{ .reg .u64 t; cvta.to.shared.u64 t, %1; cvt.u32.u64 %0, t; }" : "=r"(a) : "l"(p));
    return a;
}

__device__ __forceinline__ void cpa16(uint32_t s, const void* g) {
    asm volatile("cp.async.cg.shared.global [%0], [%1], 16;" :: "r"(s), "l"(g));
}

#define LDSM_X4(r, addr) \
    asm volatile("ldmatrix.sync.aligned.m8n8.x4.shared.b16 {%0,%1,%2,%3}, [%4];" \
        : "=r"((r)[0]), "=r"((r)[1]), "=r"((r)[2]), "=r"((r)[3]) : "r"(addr))

#define MMA_BF16(d, a, b0, b1) \
    asm volatile("mma.sync.aligned.m16n8k16.row.col.f32.bf16.bf16.f32 " \
        "{%0,%1,%2,%3}, {%4,%5,%6,%7}, {%8,%9}, {%0,%1,%2,%3};" \
        : "+f"((d)[0]), "+f"((d)[1]), "+f"((d)[2]), "+f"((d)[3]) \
        : "r"((a)[0]), "r"((a)[1]), "r"((a)[2]), "r"((a)[3]), "r"(b0), "r"(b1))

__device__ __forceinline__ void split2(float v, __nv_bfloat16& h, __nv_bfloat16& l) {
    h = __float2bfloat16(v);
    l = __float2bfloat16(v - __bfloat162float(h));
}

// ======================= mma.sync split-bf16 GEMM ===========================
// CTA tile 128x64, 4 warps (2m x 2n), warp tile 64x32, 2-stage cp.async,
// 96KB smem -> 2 CTAs/SM for cross-CTA latency hiding.
// D[m,n] = sum_k (Ah+Al)[m,k]*(Bh+Bl)[n,k]  (drops lo*lo term)
// MODE 0: fp32 out, C = acc*scale + bias[n]
// MODE 1: bf16 hi/lo out at [m*ldc + n]
// MODE 2: bf16 hi/lo out TRANSPOSED at [n*ldc + m], acc += bias[n] first
#define KT 64
#define NTHREADS 128
#define OFF_AL 16384
#define OFF_BH 32768
#define OFF_BL 40960
#define STAGE_B 49152     // Ah 16K + Al 16K + Bh 8K + Bl 8K
#define SMEM_SZ (2 * STAGE_B)   // 96KB

__device__ __forceinline__ void stage_load(uint32_t sb, int stage,
    const __nv_bfloat16* __restrict__ pAh, const __nv_bfloat16* __restrict__ pAl,
    const __nv_bfloat16* __restrict__ pBh, const __nv_bfloat16* __restrict__ pBl,
    int k0, int K, int tid)
{
    const uint32_t base = sb + stage * STAGE_B;
#pragma unroll
    for (int it = 0; it < 8; it++) {
        const int id = tid + it * NTHREADS;     // 0..1023 (128 rows x 8 chunks)
        const int row = id >> 3, c = id & 7;
        const uint32_t so = (uint32_t)(row * 128) + (((uint32_t)c << 4) ^ (((uint32_t)(row & 7)) << 4));
        const ll go = (ll)row * K + k0 + c * 8;
        cpa16(base +          so, pAh + go);
        cpa16(base + OFF_AL + so, pAl + go);
    }
#pragma unroll
    for (int it = 0; it < 4; it++) {
        const int id = tid + it * NTHREADS;     // 0..511 (64 rows x 8 chunks)
        const int row = id >> 3, c = id & 7;
        const uint32_t so = (uint32_t)(row * 128) + (((uint32_t)c << 4) ^ (((uint32_t)(row & 7)) << 4));
        const ll go = (ll)row * K + k0 + c * 8;
        cpa16(base + OFF_BH + so, pBh + go);
        cpa16(base + OFF_BL + so, pBl + go);
    }
    asm volatile("cp.async.commit_group;" ::: "memory");
}

template <int MODE>
__global__ void __launch_bounds__(NTHREADS, 2)
mma_gemm(const __nv_bfloat16* __restrict__ Ah, const __nv_bfloat16* __restrict__ Al,
         const __nv_bfloat16* __restrict__ Bh, const __nv_bfloat16* __restrict__ Bl,
         int K, ll sA, ll sB,
         float* __restrict__ C0, __nv_bfloat16* __restrict__ Ch, __nv_bfloat16* __restrict__ Cl,
         ll sC, int ldc, float scale, const float* __restrict__ bias, ll sBias)
{
    extern __shared__ char smem[];
    const uint32_t sb = smem_u32(smem);
    const int tid = threadIdx.x, wid = tid >> 5, lane = tid & 31;
    const int m0 = blockIdx.y * 128, n0 = blockIdx.x * 64, bz = blockIdx.z;

    const __nv_bfloat16* pAh = Ah + (ll)bz * sA + (ll)m0 * K;
    const __nv_bfloat16* pAl = Al + (ll)bz * sA + (ll)m0 * K;
    const __nv_bfloat16* pBh = Bh + (ll)bz * sB + (ll)n0 * K;
    const __nv_bfloat16* pBl = Bl + (ll)bz * sB + (ll)n0 * K;

    const int wm = (wid & 1) * 64;      // 2 m-groups of 64
    const int wn = (wid >> 1) * 32;     // 2 n-groups of 32

    // ldmatrix lane addressing (swizzle xor depends only on row&7)
    const int a_row = lane & 15;
    const uint32_t a_cb = ((uint32_t)(lane >> 4)) << 4;
    const uint32_t swzA = ((uint32_t)(a_row & 7)) << 4;
    const int b_row = ((lane >> 4) << 3) + (lane & 7);
    const uint32_t b_cb = ((uint32_t)((lane >> 3) & 1)) << 4;
    const uint32_t swzB = ((uint32_t)(b_row & 7)) << 4;

    float acc[4][4][4];
#pragma unroll
    for (int i = 0; i < 4; i++)
#pragma unroll
        for (int j = 0; j < 4; j++)
#pragma unroll
            for (int e = 0; e < 4; e++) acc[i][j][e] = 0.f;

    const int nk = K / KT;
    stage_load(sb, 0, pAh, pAl, pBh, pBl, 0, K, tid);

    for (int kt = 0; kt < nk; kt++) {
        const int buf = kt & 1;
        if (kt + 1 < nk) {
            stage_load(sb, buf ^ 1, pAh, pAl, pBh, pBl, (kt + 1) * KT, K, tid);
            asm volatile("cp.async.wait_group 1;" ::: "memory");
        } else {
            asm volatile("cp.async.wait_group 0;" ::: "memory");
        }
        __syncthreads();

        const uint32_t sbase = sb + buf * STAGE_B;
#pragma unroll
        for (int ks = 0; ks < 4; ks++) {
            const uint32_t kb = (uint32_t)(ks * 32);
            uint32_t ahf[4][4], alf[4][4], bhf[2][4], blf[2][4];
#pragma unroll
            for (int mt = 0; mt < 4; mt++) {
                const uint32_t ra = sbase + (uint32_t)((wm + mt * 16 + a_row) * 128)
                                  + ((kb + a_cb) ^ swzA);
                LDSM_X4(ahf[mt], ra);
                LDSM_X4(alf[mt], ra + OFF_AL);
            }
#pragma unroll
            for (int g = 0; g < 2; g++) {
                const uint32_t rb = sbase + OFF_BH + (uint32_t)((wn + g * 16 + b_row) * 128)
                                  + ((kb + b_cb) ^ swzB);
                LDSM_X4(bhf[g], rb);
                LDSM_X4(blf[g], rb + (OFF_BL - OFF_BH));
            }
            // term-major issue (16 independent MMAs between acc reuses)
#pragma unroll
            for (int mt = 0; mt < 4; mt++)
#pragma unroll
                for (int nt = 0; nt < 4; nt++) {
                    const uint32_t* bh2 = &bhf[nt >> 1][(nt & 1) * 2];
                    MMA_BF16(acc[mt][nt], ahf[mt], bh2[0], bh2[1]);
                }
#pragma unroll
            for (int mt = 0; mt < 4; mt++)
#pragma unroll
                for (int nt = 0; nt < 4; nt++) {
                    const uint32_t* bl2 = &blf[nt >> 1][(nt & 1) * 2];
                    MMA_BF16(acc[mt][nt], ahf[mt], bl2[0], bl2[1]);
                }
#pragma unroll
            for (int mt = 0; mt < 4; mt++)
#pragma unroll
                for (int nt = 0; nt < 4; nt++) {
                    const uint32_t* bh2 = &bhf[nt >> 1][(nt & 1) * 2];
                    MMA_BF16(acc[mt][nt], alf[mt], bh2[0], bh2[1]);
                }
        }
        __syncthreads();
    }

    // ---------------- epilogue (accumulators in registers) ----------------
    const int er = lane >> 2;          // 0..7
    const int ec = (lane & 3) * 2;     // 0,2,4,6
#pragma unroll
    for (int mt = 0; mt < 4; mt++) {
#pragma unroll
        for (int nt = 0; nt < 4; nt++) {
            const float* a4 = acc[mt][nt];
            const int mA = m0 + wm + mt * 16 + er;
            const int nA = n0 + wn + nt * 8 + ec;
            if (MODE == 0) {
                const float2 bb = *reinterpret_cast<const float2*>(bias + (ll)bz * sBias + nA);
                float2 v0, v1;
                v0.x = a4[0] * scale + bb.x;
                v0.y = a4[1] * scale + bb.y;
                v1.x = a4[2] * scale + bb.x;
                v1.y = a4[3] * scale + bb.y;
                *reinterpret_cast<float2*>(C0 + (ll)bz * sC + (ll)mA * ldc + nA) = v0;
                *reinterpret_cast<float2*>(C0 + (ll)bz * sC + (ll)(mA + 8) * ldc + nA) = v1;
            } else if (MODE == 1) {
                __nv_bfloat16 h0, l0, h1, l1;
                split2(a4[0], h0, l0);
                split2(a4[1], h1, l1);
                __nv_bfloat162 hv, lv;
                hv.x = h0; hv.y = h1; lv.x = l0; lv.y = l1;
                const ll c0 = (ll)bz * sC + (ll)mA * ldc + nA;
                *reinterpret_cast<__nv_bfloat162*>(Ch + c0) = hv;
                *reinterpret_cast<__nv_bfloat162*>(Cl + c0) = lv;
                split2(a4[2], h0, l0);
                split2(a4[3], h1, l1);
                hv.x = h0; hv.y = h1; lv.x = l0; lv.y = l1;
                const ll c1 = (ll)bz * sC + (ll)(mA + 8) * ldc + nA;
                *reinterpret_cast<__nv_bfloat162*>(Ch + c1) = hv;
                *reinterpret_cast<__nv_bfloat162*>(Cl + c1) = lv;
            } else {
                const float b0 = bias[(ll)bz * sBias + nA];
                const float b1 = bias[(ll)bz * sBias + nA + 1];
                __nv_bfloat16 h, l;
                const ll base = (ll)bz * sC;
                split2(a4[0] + b0, h, l);
                Ch[base + (ll)nA * ldc + mA] = h;       Cl[base + (ll)nA * ldc + mA] = l;
                split2(a4[1] + b1, h, l);
                Ch[base + (ll)(nA + 1) * ldc + mA] = h; Cl[base + (ll)(nA + 1) * ldc + mA] = l;
                split2(a4[2] + b0, h, l);
                Ch[base + (ll)nA * ldc + mA + 8] = h;       Cl[base + (ll)nA * ldc + mA + 8] = l;
                split2(a4[3] + b1, h, l);
                Ch[base + (ll)(nA + 1) * ldc + mA + 8] = h; Cl[base + (ll)(nA + 1) * ldc + mA + 8] = l;
            }
        }
    }
}

// ======================= small helper kernels ===============================
// dual split: blocks [0,64) -> src0, [64,128) -> src1   (1024x1024 each)
__global__ void split_qk_kernel(const float* __restrict__ src0, __nv_bfloat16* __restrict__ hi0,
                                __nv_bfloat16* __restrict__ lo0,
                                const float* __restrict__ src1, __nv_bfloat16* __restrict__ hi1,
                                __nv_bfloat16* __restrict__ lo1)
{
    const float* src = (blockIdx.x < 64) ? src0 : src1;
    __nv_bfloat16* hi = (blockIdx.x < 64) ? hi0 : hi1;
    __nv_bfloat16* lo = (blockIdx.x < 64) ? lo0 : lo1;
    const int bx = (blockIdx.x < 64) ? blockIdx.x : blockIdx.x - 64;
    const ll n4 = (ll)DD * DD / 4;
    ll i = (ll)bx * blockDim.x + threadIdx.x;
    const ll stride = (ll)64 * blockDim.x;
    for (; i < n4; i += stride) {
        float4 v = reinterpret_cast<const float4*>(src)[i];
        __nv_bfloat16 h0, h1, h2, h3, l0, l1, l2, l3;
        split2(v.x, h0, l0); split2(v.y, h1, l1);
        split2(v.z, h2, l2); split2(v.w, h3, l3);
        __nv_bfloat162 a, b, c, d;
        a.x = h0; a.y = h1; b.x = h2; b.y = h3;
        c.x = l0; c.y = l1; d.x = l2; d.y = l3;
        reinterpret_cast<__nv_bfloat162*>(hi)[i * 2 + 0] = a;
        reinterpret_cast<__nv_bfloat162*>(hi)[i * 2 + 1] = b;
        reinterpret_cast<__nv_bfloat162*>(lo)[i * 2 + 0] = c;
        reinterpret_cast<__nv_bfloat162*>(lo)[i * 2 + 1] = d;
    }
}

__global__ void split_kernel(const float* __restrict__ src, __nv_bfloat16* __restrict__ hi,
                             __nv_bfloat16* __restrict__ lo, ll n4)
{
    ll i = (ll)blockIdx.x * blockDim.x + threadIdx.x;
    const ll stride = (ll)gridDim.x * blockDim.x;
    for (; i < n4; i += stride) {
        float4 v = reinterpret_cast<const float4*>(src)[i];
        __nv_bfloat16 h0, h1, h2, h3, l0, l1, l2, l3;
        split2(v.x, h0, l0); split2(v.y, h1, l1);
        split2(v.z, h2, l2); split2(v.w, h3, l3);
        __nv_bfloat162 a, b, c, d;
        a.x = h0; a.y = h1; b.x = h2; b.y = h3;
        c.x = l0; c.y = l1; d.x = l2; d.y = l3;
        reinterpret_cast<__nv_bfloat162*>(hi)[i * 2 + 0] = a;
        reinterpret_cast<__nv_bfloat162*>(hi)[i * 2 + 1] = b;
        reinterpret_cast<__nv_bfloat162*>(lo)[i * 2 + 0] = c;
        reinterpret_cast<__nv_bfloat162*>(lo)[i * 2 + 1] = d;
    }
}

// Wt[n,e] = Wv[D+e, n]  (transpose + split)
__global__ void tsplit_wv(const float* __restrict__ Wv, __nv_bfloat16* __restrict__ Wth,
                          __nv_bfloat16* __restrict__ Wtl)
{
    __shared__ float t[32][33];
    const int tx = threadIdx.x, ty = threadIdx.y;
    const int bx = blockIdx.x, by = blockIdx.y;
    const int x = bx * 32 + tx;
#pragma unroll
    for (int j = 0; j < 4; j++) {
        const int y = by * 32 + ty + j * 8;
        t[ty + j * 8][tx] = Wv[(ll)(DD + y) * DD + x];
    }
    __syncthreads();
#pragma unroll
    for (int j = 0; j < 4; j++) {
        const int n = bx * 32 + ty + j * 8;
        const int d = by * 32 + tx;
        __nv_bfloat16 h, l;
        split2(t[tx][ty + j * 8], h, l);
        Wth[(ll)n * DD + d] = h;
        Wtl[(ll)n * DD + d] = l;
    }
}

__global__ void rowdot_kernel(const float* __restrict__ X, const float* __restrict__ vec,
                              float* __restrict__ out, int nrows, float scale)
{
    const int warp = (blockIdx.x * blockDim.x + threadIdx.x) >> 5;
    const int lane = threadIdx.x & 31;
    if (warp >= nrows) return;
    const float4* r = reinterpret_cast<const float4*>(X + (ll)warp * DD);
    const float4* v = reinterpret_cast<const float4*>(vec);
    float acc = 0.f;
#pragma unroll
    for (int i = 0; i < 8; i++) {
        float4 a = r[lane + 32 * i];
        float4 b = v[lane + 32 * i];
        acc += a.x * b.x + a.y * b.y + a.z * b.z + a.w * b.w;
    }
#pragma unroll
    for (int off = 16; off; off >>= 1)
        acc += __shfl_xor_sync(0xffffffffu, acc, off);
    if (lane == 0) out[warp] = scale * acc;
}

__global__ void vb1_kernel(const float* __restrict__ X1, const float* __restrict__ Wv,
                           const float* __restrict__ bv, float* __restrict__ vb1)
{
    __shared__ float x1s[BB * DD];
    const int tid = threadIdx.x;  // 128
    for (int i = tid; i < BB * DD; i += 128) x1s[i] = X1[i];
    __syncthreads();
    const int o = blockIdx.x * 128 + tid;
    float acc[BB];
#pragma unroll
    for (int b = 0; b < BB; b++) acc[b] = 0.f;
    for (int i = 0; i < DD; i++) {
        const float wv = Wv[(ll)i * DD + o];
#pragma unroll
        for (int b = 0; b < BB; b++) acc[b] = fmaf(x1s[b * DD + i], wv, acc[b]);
    }
    const float bvo = bv[o];
#pragma unroll
    for (int b = 0; b < BB; b++) vb1[b * DD + o] = acc[b] + bvo;
}

// row softmax over 2048 fp32 scores -> bf16 hi/lo probs
__global__ void __launch_bounds__(256) softmax_rows(const float* __restrict__ A,
                                                    __nv_bfloat16* __restrict__ Ph,
                                                    __nv_bfloat16* __restrict__ Pl)
{
    const float* p = A + (ll)blockIdx.x * SS;
    const int tid = threadIdx.x;
    const int lane = tid & 31, wid = tid >> 5;
    const float4* pv = reinterpret_cast<const float4*>(p);
    float4 v0 = pv[tid];
    float4 v1 = pv[tid + 256];

    float m = fmaxf(fmaxf(fmaxf(v0.x, v0.y), fmaxf(v0.z, v0.w)),
                    fmaxf(fmaxf(v1.x, v1.y), fmaxf(v1.z, v1.w)));
#pragma unroll
    for (int off = 16; off; off >>= 1) m = fmaxf(m, __shfl_xor_sync(0xffffffffu, m, off));
    __shared__ float smax[8], ssum[8];
    if (lane == 0) smax[wid] = m;
    __syncthreads();
    float mall = smax[0];
#pragma unroll
    for (int i = 1; i < 8; i++) mall = fmaxf(mall, smax[i]);

    v0.x = __expf(v0.x - mall); v0.y = __expf(v0.y - mall);
    v0.z = __expf(v0.z - mall); v0.w = __expf(v0.w - mall);
    v1.x = __expf(v1.x - mall); v1.y = __expf(v1.y - mall);
    v1.z = __expf(v1.z - mall); v1.w = __expf(v1.w - mall);

    float s = v0.x + v0.y + v0.z + v0.w + v1.x + v1.y + v1.z + v1.w;
#pragma unroll
    for (int off = 16; off; off >>= 1) s += __shfl_xor_sync(0xffffffffu, s, off);
    if (lane == 0) ssum[wid] = s;
    __syncthreads();
    float tot = 0.f;
#pragma unroll
    for (int i = 0; i < 8; i++) tot += ssum[i];
    const float inv = 1.f / tot;

    __nv_bfloat162* ph = reinterpret_cast<__nv_bfloat162*>(Ph + (ll)blockIdx.x * SS);
    __nv_bfloat162* pl = reinterpret_cast<__nv_bfloat162*>(Pl + (ll)blockIdx.x * SS);

    auto emit = [&](float a, float b, int idx) {
        __nv_bfloat16 ah, al, bh, bl;
        split2(a * inv, ah, al);
        split2(b * inv, bh, bl);
        __nv_bfloat162 hv; hv.x = ah; hv.y = bh;
        __nv_bfloat162 lv; lv.x = al; lv.y = bl;
        ph[idx] = hv;
        pl[idx] = lv;
    };
    emit(v0.x, v0.y, tid * 2 + 0);
    emit(v0.z, v0.w, tid * 2 + 1);
    emit(v1.x, v1.y, 512 + tid * 2 + 0);
    emit(v1.z, v1.w, 512 + tid * 2 + 1);
}

// negV[b,n] = -(alpha/S) * sum_k Vt[b,n,k]
__global__ void vtsum_kernel(const __nv_bfloat16* __restrict__ Vth,
                             const __nv_bfloat16* __restrict__ Vtl,
                             const float* __restrict__ alpha, float* __restrict__ negV)
{
    const int row = blockIdx.x * 8 + (threadIdx.x >> 5);
    const int lane = threadIdx.x & 31;
    const __nv_bfloat162* ph = reinterpret_cast<const __nv_bfloat162*>(Vth + (ll)row * SS);
    const __nv_bfloat162* pl = reinterpret_cast<const __nv_bfloat162*>(Vtl + (ll)row * SS);
    float acc = 0.f;
#pragma unroll
    for (int i = 0; i < 32; i++) {
        __nv_bfloat162 a = ph[lane + 32 * i];
        __nv_bfloat162 b = pl[lane + 32 * i];
        acc += __bfloat162float(a.x) + __bfloat162float(a.y)
             + __bfloat162float(b.x) + __bfloat162float(b.y);
    }
#pragma unroll
    for (int off = 16; off; off >>= 1)
        acc += __shfl_xor_sync(0xffffffffu, acc, off);
    if (lane == 0) negV[row] = -(alpha[0] / (float)SS) * acc;
}

// ======================= launch =============================================
extern "C" void kernel_launch(void* const* d_in, const int* in_sizes, int n_in,
                              void* d_out, int out_size)
{
    (void)in_sizes; (void)n_in; (void)out_size;
    const float* X1   = (const float*)d_in[0];
    const float* X2   = (const float*)d_in[1];
    const float* Wq2  = (const float*)d_in[4];
    const float* bq2  = (const float*)d_in[5];
    const float* Wk2  = (const float*)d_in[8];
    const float* Wv   = (const float*)d_in[10];
    const float* bv   = (const float*)d_in[11];
    const float* alph = (const float*)d_in[12];
    float* out = (float*)d_out;
    const float s = 0.03125f;  // 1/sqrt(1024)

    cudaFuncSetAttribute(mma_gemm<0>, cudaFuncAttributeMaxDynamicSharedMemorySize, SMEM_SZ);
    cudaFuncSetAttribute(mma_gemm<1>, cudaFuncAttributeMaxDynamicSharedMemorySize, SMEM_SZ);
    cudaFuncSetAttribute(mma_gemm<2>, cudaFuncAttributeMaxDynamicSharedMemorySize, SMEM_SZ);

    void* p;
    cudaGetSymbolAddress(&p, g_A);    float* pA   = (float*)p;
    cudaGetSymbolAddress(&p, g_x2h);  __nv_bfloat16* x2h = (__nv_bfloat16*)p;
    cudaGetSymbolAddress(&p, g_x2l);  __nv_bfloat16* x2l = (__nv_bfloat16*)p;
    cudaGetSymbolAddress(&p, g_q2h);  __nv_bfloat16* q2h = (__nv_bfloat16*)p;
    cudaGetSymbolAddress(&p, g_q2l);  __nv_bfloat16* q2l = (__nv_bfloat16*)p;
    cudaGetSymbolAddress(&p, g_k2h);  __nv_bfloat16* k2h = (__nv_bfloat16*)p;
    cudaGetSymbolAddress(&p, g_k2l);  __nv_bfloat16* k2l = (__nv_bfloat16*)p;
    cudaGetSymbolAddress(&p, g_mth);  __nv_bfloat16* mth = (__nv_bfloat16*)p;
    cudaGetSymbolAddress(&p, g_mtl);  __nv_bfloat16* mtl = (__nv_bfloat16*)p;
    cudaGetSymbolAddress(&p, g_wth);  __nv_bfloat16* wth = (__nv_bfloat16*)p;
    cudaGetSymbolAddress(&p, g_wtl);  __nv_bfloat16* wtl = (__nv_bfloat16*)p;
    cudaGetSymbolAddress(&p, g_gh);   __nv_bfloat16* gh  = (__nv_bfloat16*)p;
    cudaGetSymbolAddress(&p, g_gl);   __nv_bfloat16* gl  = (__nv_bfloat16*)p;
    cudaGetSymbolAddress(&p, g_vth);  __nv_bfloat16* vth = (__nv_bfloat16*)p;
    cudaGetSymbolAddress(&p, g_vtl);  __nv_bfloat16* vtl = (__nv_bfloat16*)p;
    cudaGetSymbolAddress(&p, g_ph);   __nv_bfloat16* ph  = (__nv_bfloat16*)p;
    cudaGetSymbolAddress(&p, g_pl);   __nv_bfloat16* pl  = (__nv_bfloat16*)p;
    cudaGetSymbolAddress(&p, g_tvec); float* ptvec = (float*)p;
    cudaGetSymbolAddress(&p, g_vb1);  float* pvb1  = (float*)p;
    cudaGetSymbolAddress(&p, g_sw);   float* psw   = (float*)p;
    cudaGetSymbolAddress(&p, g_negV); float* pnegV = (float*)p;

    // Launch order arranged so the 4th launch is the G GEMM (ncu lands there).
    // 1. dual weight split
    split_qk_kernel<<<128, 256>>>(Wq2, q2h, q2l, Wk2, k2h, k2l);
    // 2. X2 split
    split_kernel<<<2048, 256>>>(X2, x2h, x2l, (ll)BSROWS * DD / 4);
    // 3. Mt = Wk2 @ Wq2^T -> hi/lo
    mma_gemm<1><<<dim3(16, 8, 1), NTHREADS, SMEM_SZ>>>(
        k2h, k2l, q2h, q2l, DD, 0, 0,
        nullptr, mth, mtl, 0, DD, 1.f, nullptr, 0);
    // 4. G = X2 @ M  -> hi/lo      (PROFILED LAUNCH)
    mma_gemm<1><<<dim3(16, 16, 8), NTHREADS, SMEM_SZ>>>(
        x2h, x2l, mth, mtl, DD, (ll)SS * DD, 0,
        nullptr, gh, gl, (ll)SS * DD, DD, 1.f, nullptr, 0);
    // 5-8. V-chain precomputes
    tsplit_wv<<<dim3(32, 32), dim3(32, 8)>>>(Wv, wth, wtl);
    vb1_kernel<<<DD / 128, 128>>>(X1, Wv, bv, pvb1);
    rowdot_kernel<<<DD / 8, 256>>>(Wk2, bq2, ptvec, DD, 1.f);
    rowdot_kernel<<<BSROWS / 8, 256>>>(X2, ptvec, psw, BSROWS, s);
    // 9. V = X2 @ Wv2 + vb1 -> transposed hi/lo [b][d][s]
    mma_gemm<2><<<dim3(16, 16, 8), NTHREADS, SMEM_SZ>>>(
        x2h, x2l, wth, wtl, DD, (ll)SS * DD, 0,
        nullptr, vth, vtl, (ll)DD * SS, SS, 1.f, pvb1, DD);
    // 10. negV from Vt row sums
    vtsum_kernel<<<1024, 256>>>(vth, vtl, alph, pnegV);
    // 11. scores = s*(G @ X2^T) + sw[k]  (fp32)
    mma_gemm<0><<<dim3(32, 16, 8), NTHREADS, SMEM_SZ>>>(
        gh, gl, x2h, x2l, DD, (ll)SS * DD, (ll)SS * DD,
        pA, nullptr, nullptr, (ll)SS * SS, SS, s, psw, SS);
    // 12. softmax -> P hi/lo
    softmax_rows<<<BSROWS, 256>>>(pA, ph, pl);
    // 13. out = P @ V + negV
    mma_gemm<0><<<dim3(16, 16, 8), NTHREADS, SMEM_SZ>>>(
        ph, pl, vth, vtl, SS, (ll)SS * SS, (ll)DD * SS,
        out, nullptr, nullptr, (ll)SS * DD, DD, 1.f, pnegV, DD);
}